// round 14
// baseline (speedup 1.0000x reference)
#include <cuda_runtime.h>
#include <cuda_fp16.h>
#include <math.h>
#include <stdint.h>

#define M_ROWS 65536
#define B_ROWS 2048
#define D_IN   13
#define H1N    300
#define H2N    600
#define H3N    100
#define EPS_F  1e-8f
#define SCALE_F 23.0f
#define SLOPE  0.01f

extern __shared__ char dynsmem[];

// ============ scratch (device globals; no allocations) ============
// fp16 2-section scheme: computes Ah*(Wh+Wl) with one A pass.
__device__ uint4 g_A2h[65536ULL * 40];   // [65536][320] fp16
__device__ uint4 g_A3h[65536ULL * 80];   // [65536][640] fp16
__device__ uint4 g_W2h[640 * 40];
__device__ uint4 g_W2l[640 * 40];
__device__ uint4 g_W3h[128 * 80];
__device__ uint4 g_W3l[128 * 80];
__device__ uint4 g_vns[B_ROWS * 4];      // [Vh|Vh], 32 fp16/row
__device__ uint4 g_t1s[65536ULL * 4];    // [Th|Tl], 32 fp16/row
__device__ unsigned int g_umax[B_ROWS];

__device__ __forceinline__ unsigned fkey(float f) {
    unsigned b = __float_as_uint(f);
    return (b & 0x80000000u) ? ~b : (b | 0x80000000u);
}
__device__ __forceinline__ float funkey(unsigned u) {
    unsigned b = (u & 0x80000000u) ? (u ^ 0x80000000u) : ~u;
    return __uint_as_float(b);
}
__device__ __forceinline__ uint32_t pk2h(float a, float b) {
    __half2 t = __floats2half2_rn(a, b);
    return *reinterpret_cast<uint32_t*>(&t);
}
__device__ __forceinline__ uint32_t smem_u32(const void* p) {
    uint32_t a;
    asm("{ .reg .u64 t; cvta.to.shared.u64 t, %1; cvt.u32.u64 %0, t; }" : "=r"(a) : "l"(p));
    return a;
}
__device__ __forceinline__ void mma16816(float* d, const uint32_t* a, const uint32_t* b) {
    asm volatile(
        "mma.sync.aligned.m16n8k16.row.col.f32.f16.f16.f32 "
        "{%0,%1,%2,%3}, {%4,%5,%6,%7}, {%8,%9}, {%0,%1,%2,%3};"
        : "+f"(d[0]), "+f"(d[1]), "+f"(d[2]), "+f"(d[3])
        : "r"(a[0]), "r"(a[1]), "r"(a[2]), "r"(a[3]), "r"(b[0]), "r"(b[1]));
}
__device__ __forceinline__ void ldm_x4(uint32_t* r, uint32_t addr) {
    asm volatile("ldmatrix.sync.aligned.m8n8.x4.shared.b16 {%0,%1,%2,%3}, [%4];"
        : "=r"(r[0]), "=r"(r[1]), "=r"(r[2]), "=r"(r[3]) : "r"(addr));
}
__device__ __forceinline__ void ldm_x2(uint32_t* r, uint32_t addr) {
    asm volatile("ldmatrix.sync.aligned.m8n8.x2.shared.b16 {%0,%1}, [%2];"
        : "=r"(r[0]), "=r"(r[1]) : "r"(addr));
}
__device__ __forceinline__ void cpa16(uint32_t dst, const void* src) {
    asm volatile("cp.async.cg.shared.global [%0], [%1], 16;" :: "r"(dst), "l"(src));
}
#define CP_COMMIT() asm volatile("cp.async.commit_group;" ::: "memory")
#define CP_WAIT(n)  asm volatile("cp.async.wait_group %0;" :: "n"(n) : "memory")

// ---------- merged prep: W2 (0-99), W3 (100-139), vn (140-147) ----------
__global__ void __launch_bounds__(256)
prep_all_kernel(const float* __restrict__ W2, const float* __restrict__ W3,
                const float* __restrict__ value) {
    const int blk = blockIdx.x, tid = threadIdx.x;
    if (blk < 100) {
        int e = blk * 256 + tid;                   // [640][40] uint4
        int n = e / 40, c8 = e % 40;
        union { uint4 v; __half b[8]; } hu, lu;
        #pragma unroll
        for (int t = 0; t < 8; t++) {
            int k = c8 * 8 + t;
            float w = (n < H2N && k < H1N) ? W2[n * H1N + k] : 0.f;
            __half h = __float2half_rn(w);
            hu.b[t] = h;
            lu.b[t] = __float2half_rn(w - __half2float(h));
        }
        g_W2h[e] = hu.v;
        g_W2l[e] = lu.v;
    } else if (blk < 140) {
        int e = (blk - 100) * 256 + tid;           // [128][80] uint4
        int n = e / 80, c8 = e % 80;
        union { uint4 v; __half b[8]; } hu, lu;
        #pragma unroll
        for (int t = 0; t < 8; t++) {
            int k = c8 * 8 + t;
            float w = (n < H3N && k < H2N) ? W3[n * H2N + k] : 0.f;
            __half h = __float2half_rn(w);
            hu.b[t] = h;
            lu.b[t] = __float2half_rn(w - __half2float(h));
        }
        g_W3h[e] = hu.v;
        g_W3l[e] = lu.v;
    } else {
        int t = (blk - 140) * 256 + tid;
        if (t < B_ROWS) {
            float v[16], s = 0.f;
            #pragma unroll
            for (int o = 0; o < 16; o++) v[o] = 0.f;
            #pragma unroll
            for (int o = 0; o < D_IN; o++) { v[o] = value[t * D_IN + o]; s += v[o] * v[o]; }
            float inv = 1.f / fmaxf(sqrtf(s), EPS_F);
            union { uint4 q[4]; uint32_t u[16]; } out;
            #pragma unroll
            for (int o = 0; o < 16; o += 2) {
                uint32_t vh = pk2h(v[o] * inv, v[o + 1] * inv);
                out.u[o / 2]     = vh;
                out.u[8 + o / 2] = vh;
            }
            #pragma unroll
            for (int j = 0; j < 4; j++) g_vns[t * 4 + j] = out.q[j];
            g_umax[t] = 0u;
        }
    }
}

// ---------- layer 1: 13 -> 300 relu, fp16 out ----------
#define L1_SW   0
#define L1_SB   20480
#define L1_SX   21760
#define L1_SMEM 32000
__global__ void __launch_bounds__(256)
layer1_kernel(const float* __restrict__ memx, const float* __restrict__ W1,
              const float* __restrict__ b1) {
    float* sW = (float*)(dynsmem + L1_SW);   // [320][16]
    float* sb = (float*)(dynsmem + L1_SB);   // [320]
    float* sx = (float*)(dynsmem + L1_SX);   // [128][20]
    const int tid = threadIdx.x;
    const int m0 = blockIdx.x * 128;
    const int row = tid & 127, half = tid >> 7;

    for (int i = tid; i < 320 * 16; i += 256) sW[i] = 0.f;
    for (int i = tid; i < 320; i += 256) sb[i] = (i < H1N) ? b1[i] : 0.f;
    for (int i = tid; i < 128 * 20; i += 256) sx[i] = 0.f;
    __syncthreads();
    for (int i = tid; i < H1N * D_IN; i += 256) sW[(i / D_IN) * 16 + (i % D_IN)] = W1[i];
    for (int i = tid; i < 128 * D_IN; i += 256) sx[(i / D_IN) * 20 + (i % D_IN)] = memx[(size_t)m0 * D_IN + i];
    __syncthreads();

    float4 xv[4];
    #pragma unroll
    for (int j = 0; j < 4; j++) xv[j] = *(float4*)(&sx[row * 20 + 4 * j]);

    const size_t rbase = (size_t)(m0 + row) * 40 + half * 20;
    #pragma unroll 1
    for (int gg = 0; gg < 10; gg++) {
        uint4 hq[2];
        #pragma unroll
        for (int g2 = 0; g2 < 2; g2++) {
            union { uint4 v; uint32_t u[4]; } hv;
            #pragma unroll
            for (int p = 0; p < 4; p++) {
                float o2[2];
                #pragma unroll
                for (int e = 0; e < 2; e++) {
                    int c = (half * 20 + gg * 2 + g2) * 8 + p * 2 + e;
                    float acc = sb[c];
                    #pragma unroll
                    for (int j = 0; j < 4; j++) {
                        float4 w = *(float4*)(&sW[c * 16 + 4 * j]);
                        acc += xv[j].x * w.x + xv[j].y * w.y + xv[j].z * w.z + xv[j].w * w.w;
                    }
                    o2[e] = fmaxf(acc, 0.f);
                }
                hv.u[p] = pk2h(o2[0], o2[1]);
            }
            hq[g2] = hv.v;
        }
        g_A2h[rbase + gg * 2] = hq[0];
        g_A2h[rbase + gg * 2 + 1] = hq[1];
    }
}

// ---------- fp16 mma GEMM: merged stage [A | Wh | Wl], 2-stage cp.async ----------
// MODE 2: 128x128 tile, NK=5;  MODE 3: 128x104 tile, NK=10 + fused tail
#define SKEW_B 144
#define G2_STAGE ((128 + 256) * SKEW_B)               // 55296
#define G3_STAGE ((128 + 208) * SKEW_B)               // 48384
#define GEMM2_SMEM (2 * G2_STAGE)                     // 110592
#define G3_W4   (2 * G3_STAGE)                        // 96768
#define G3_B4   (G3_W4 + 5200)
#define G3_SMEM (G3_B4 + 64)                          // 102032
template<int MODE>
__global__ void __launch_bounds__(256)
gemm_kernel(const float* __restrict__ bias,
            const float* __restrict__ W4, const float* __restrict__ b4) {
    constexpr int KPU = (MODE == 2) ? 40 : 80;
    constexpr int NK  = (MODE == 2) ? 5 : 10;
    constexpr int NB  = (MODE == 2) ? 128 : 104;
    constexpr int MI  = (MODE == 2) ? 4 : 1;
    constexpr int NI  = (MODE == 2) ? 4 : 13;
    constexpr int STAGE = (MODE == 2) ? G2_STAGE : G3_STAGE;
    constexpr int BOFF  = 128 * SKEW_B;
    constexpr int WLOFF = NB * SKEW_B;                // Wl after Wh
    char* sm = dynsmem;
    const uint32_t smb = smem_u32(sm);

    const int tid = threadIdx.x;
    const int wid = tid >> 5, lane = tid & 31;
    const int gid = lane >> 2, tig = lane & 3;
    const int wy = (MODE == 2) ? (wid >> 2) : wid;
    const int wx = (MODE == 2) ? (wid & 3) : 0;
    const int m0 = blockIdx.x * 128;
    const int n0 = blockIdx.y * ((MODE == 2) ? 128 : 104);

    if (MODE == 3) {
        float* sW4 = (float*)(sm + G3_W4);
        float* sb4 = (float*)(sm + G3_B4);
        for (int i = tid; i < D_IN * H3N; i += 256) sW4[i] = W4[i];
        if (tid < D_IN) sb4[tid] = b4[tid];
    }

    float acc[MI][NI][4];
    #pragma unroll
    for (int mi = 0; mi < MI; mi++)
        #pragma unroll
        for (int ni = 0; ni < NI; ni++)
            #pragma unroll
            for (int q = 0; q < 4; q++) acc[mi][ni][q] = 0.f;

    const int lrow = lane & 15, lkh = lane >> 4;
    uint32_t aoff[MI], boff[(NI + 1) / 2];
    #pragma unroll
    for (int mi = 0; mi < MI; mi++) {
        int r = ((MODE == 2) ? (wy * 64 + mi * 16) : (wy * 16)) + lrow;
        aoff[mi] = smb + r * SKEW_B + lkh * 16;
    }
    #pragma unroll
    for (int p = 0; p < (NI + 1) / 2; p++) {
        int nb = wx * 32 + p * 16;
        if (2 * p + 1 < NI || MODE == 2) {
            boff[p] = smb + BOFF + (nb + lrow) * SKEW_B + lkh * 16;
        } else {
            int l16 = lane & 15;
            boff[p] = smb + BOFF + (96 + (l16 & 7)) * SKEW_B + (l16 >> 3) * 16;
        }
    }

    constexpr int TOT8 = (128 + 2 * NB) * 8;
    constexpr int NLD = (TOT8 + 255) / 256;
    auto issue_copy = [&](int kc, int st) {
        const uint4* Asrc = (MODE == 2) ? g_A2h : g_A3h;
        const uint4* Wh = (MODE == 2) ? g_W2h : g_W3h;
        const uint4* Wl = (MODE == 2) ? g_W2l : g_W3l;
        int k0u = kc * 8;
        uint32_t sb0 = smb + st * STAGE;
        #pragma unroll
        for (int j = 0; j < NLD; j++) {
            int u = tid + j * 256;
            if (u < TOT8) {
                int row = u >> 3, uu = u & 7;
                const uint4* src;
                uint32_t dst;
                if (row < 128) {
                    src = &Asrc[(size_t)(m0 + row) * KPU + k0u + uu];
                    dst = sb0 + row * SKEW_B + uu * 16;
                } else if (row < 128 + NB) {
                    src = &Wh[(size_t)(n0 + row - 128) * KPU + k0u + uu];
                    dst = sb0 + BOFF + (row - 128) * SKEW_B + uu * 16;
                } else {
                    src = &Wl[(size_t)(n0 + row - 128 - NB) * KPU + k0u + uu];
                    dst = sb0 + BOFF + WLOFF + (row - 128 - NB) * SKEW_B + uu * 16;
                }
                cpa16(dst, src);
            }
        }
        CP_COMMIT();
    };
    auto load_bf = [&](uint32_t ko, uint32_t (&bf)[NI][2]) {
        #pragma unroll
        for (int p = 0; p < NI / 2; p++) {
            uint32_t r4[4];
            ldm_x4(r4, boff[p] + ko);
            bf[2 * p][0] = r4[0]; bf[2 * p + 1][0] = r4[1];
            bf[2 * p][1] = r4[2]; bf[2 * p + 1][1] = r4[3];
        }
        if (NI & 1) ldm_x2(bf[NI - 1], boff[NI / 2] + ko);
    };
    auto compute = [&](int st) {
        const uint32_t sb0 = st * STAGE;
        #pragma unroll
        for (int ks = 0; ks < 4; ks++) {
            const uint32_t ko = sb0 + ks * 32;
            uint32_t af[MI][4];
            #pragma unroll
            for (int mi = 0; mi < MI; mi++) ldm_x4(af[mi], aoff[mi] + ko);
            uint32_t bf[NI][2];
            load_bf(ko, bf);                 // Wh
            #pragma unroll
            for (int mi = 0; mi < MI; mi++)
                #pragma unroll
                for (int ni = 0; ni < NI; ni++)
                    mma16816(acc[mi][ni], af[mi], bf[ni]);
            load_bf(ko + WLOFF, bf);         // Wl
            #pragma unroll
            for (int mi = 0; mi < MI; mi++)
                #pragma unroll
                for (int ni = 0; ni < NI; ni++)
                    mma16816(acc[mi][ni], af[mi], bf[ni]);
        }
    };

    issue_copy(0, 0);
    issue_copy(1, 1);
    for (int kc = 0; kc < NK; kc++) {
        if (kc + 1 < NK) { CP_WAIT(1); } else { CP_WAIT(0); }
        __syncthreads();
        compute(kc & 1);
        __syncthreads();
        if (kc + 2 < NK) issue_copy(kc + 2, kc & 1);
    }

    if (MODE == 2) {
        #pragma unroll
        for (int mi = 0; mi < MI; mi++) {
            #pragma unroll
            for (int ni = 0; ni < NI; ni++) {
                int r0 = m0 + wy * 64 + mi * 16 + gid;
                int c  = n0 + wx * 32 + ni * 8 + tig * 2;
                if (c < H2N) {
                    float bv0 = __ldg(&bias[c]), bv1 = __ldg(&bias[c + 1]);
                    #pragma unroll
                    for (int h = 0; h < 2; h++) {
                        int r = r0 + h * 8;
                        float v0 = acc[mi][ni][h * 2 + 0] + bv0;
                        float v1 = acc[mi][ni][h * 2 + 1] + bv1;
                        v0 = v0 > 0.f ? v0 : SLOPE * v0;
                        v1 = v1 > 0.f ? v1 : SLOPE * v1;
                        ((uint32_t*)g_A3h)[(size_t)r * 320 + (c >> 1)] = pk2h(v0, v1);
                    }
                }
            }
        }
    } else {
        // ---- fused tail: h3 -> smem, layer4 + normalize -> g_t1s split ----
        __syncthreads();
        float* h3s = (float*)sm;             // [128][106]
        #pragma unroll
        for (int ni = 0; ni < NI; ni++) {
            int c = ni * 8 + tig * 2;
            float bv0 = (c < H3N) ? __ldg(&bias[c]) : 0.f;
            float bv1 = (c + 1 < H3N) ? __ldg(&bias[c + 1]) : 0.f;
            #pragma unroll
            for (int h = 0; h < 2; h++) {
                int r = wy * 16 + gid + h * 8;
                float v0 = fmaxf(acc[0][ni][h * 2 + 0] + bv0, 0.f);
                float v1 = fmaxf(acc[0][ni][h * 2 + 1] + bv1, 0.f);
                *(float2*)(&h3s[r * 106 + c]) = make_float2(v0, v1);
            }
        }
        __syncthreads();
        if (tid < 128) {
            const float* sW4 = (const float*)(sm + G3_W4);
            const float* sb4 = (const float*)(sm + G3_B4);
            int r = tid;
            float o[D_IN];
            #pragma unroll
            for (int oo = 0; oo < D_IN; oo++) o[oo] = sb4[oo];
            #pragma unroll 4
            for (int k = 0; k < H3N; k++) {
                float hv = h3s[r * 106 + k];
                #pragma unroll
                for (int oo = 0; oo < D_IN; oo++) o[oo] += hv * sW4[oo * H3N + k];
            }
            float s = 0.f;
            #pragma unroll
            for (int oo = 0; oo < D_IN; oo++) {
                o[oo] = o[oo] > 0.f ? o[oo] : SLOPE * o[oo];
                s += o[oo] * o[oo];
            }
            float inv = 1.f / fmaxf(sqrtf(s), EPS_F);
            float t[16];
            #pragma unroll
            for (int oo = 0; oo < 16; oo++) t[oo] = (oo < D_IN) ? o[oo] * inv : 0.f;
            union { uint4 q[4]; uint32_t u[16]; } out;
            #pragma unroll
            for (int oo = 0; oo < 16; oo += 2) {
                float ah = __half2float(__float2half_rn(t[oo]));
                float bh = __half2float(__float2half_rn(t[oo + 1]));
                out.u[oo / 2]     = pk2h(t[oo], t[oo + 1]);               // Th
                out.u[8 + oo / 2] = pk2h(t[oo] - ah, t[oo + 1] - bh);     // Tl
            }
            #pragma unroll
            for (int j = 0; j < 4; j++) g_t1s[(size_t)(m0 + r) * 4 + j] = out.q[j];
        }
    }
}

// ---------- similarity via fp16 mma: Vh * (Th + Tl) ----------
#define SIM_SV  0
#define SIM_ST  (2048 * 80)
#define SIM_SMEM (SIM_ST + 128 * 80)       // 174080
__global__ void __launch_bounds__(256, 1)
sim_kernel() {
    char* sm = dynsmem;
    char* sv  = sm + SIM_SV;    // [2048][80B]
    char* st1 = sm + SIM_ST;    // [128][80B]
    const int tid = threadIdx.x;
    const int wid = tid >> 5, lane = tid & 31;
    const int gid = lane >> 2, tig = lane & 3;
    const int wy = wid >> 2, wx = wid & 3;
    const int n0 = blockIdx.x * 128;

    for (int i = tid; i < B_ROWS * 4; i += 256) {
        int r = i >> 2, q = i & 3;
        *(uint4*)(sv + r * 80 + q * 16) = g_vns[i];
    }
    for (int i = tid; i < 128 * 4; i += 256) {
        int r = i >> 2, q = i & 3;
        *(uint4*)(st1 + r * 80 + q * 16) = g_t1s[(size_t)n0 * 4 + i];
    }
    __syncthreads();

    uint32_t sbf[2][4][2];
    #pragma unroll
    for (int s = 0; s < 2; s++)
        #pragma unroll
        for (int ni = 0; ni < 4; ni++) {
            int n = wx * 32 + ni * 8 + gid;
            sbf[s][ni][0] = *(const uint32_t*)(st1 + n * 80 + s * 32 + tig * 4);
            sbf[s][ni][1] = *(const uint32_t*)(st1 + n * 80 + s * 32 + 16 + tig * 4);
        }

    for (int c = 0; c < 8; c++) {
        float acc[8][4][4];
        #pragma unroll
        for (int mi = 0; mi < 8; mi++)
            #pragma unroll
            for (int ni = 0; ni < 4; ni++)
                #pragma unroll
                for (int q = 0; q < 4; q++) acc[mi][ni][q] = 0.f;

        const char* va = sv + (c * 256 + wy * 128) * 80;
        #pragma unroll
        for (int s = 0; s < 2; s++) {
            #pragma unroll
            for (int mi = 0; mi < 8; mi++) {
                int r = mi * 16 + gid;
                uint32_t af[4];
                af[0] = *(const uint32_t*)(va + r * 80 + s * 32 + tig * 4);
                af[1] = *(const uint32_t*)(va + (r + 8) * 80 + s * 32 + tig * 4);
                af[2] = *(const uint32_t*)(va + r * 80 + s * 32 + 16 + tig * 4);
                af[3] = *(const uint32_t*)(va + (r + 8) * 80 + s * 32 + 16 + tig * 4);
                #pragma unroll
                for (int ni = 0; ni < 4; ni++)
                    mma16816(acc[mi][ni], af, sbf[s][ni]);
            }
        }
        #pragma unroll
        for (int mi = 0; mi < 8; mi++) {
            #pragma unroll
            for (int h = 0; h < 2; h++) {
                float mx = -3.4e38f;
                #pragma unroll
                for (int ni = 0; ni < 4; ni++)
                    mx = fmaxf(mx, fmaxf(acc[mi][ni][h * 2], acc[mi][ni][h * 2 + 1]));
                mx = fmaxf(mx, __shfl_xor_sync(0xFFFFFFFF, mx, 1));
                mx = fmaxf(mx, __shfl_xor_sync(0xFFFFFFFF, mx, 2));
                if (tig == 0) {
                    int row = c * 256 + wy * 128 + mi * 16 + gid + 8 * h;
                    atomicMax(&g_umax[row], fkey(SCALE_F * mx));
                }
            }
        }
    }
}

__global__ void finish_kernel(float* __restrict__ out) {
    int t = blockIdx.x * blockDim.x + threadIdx.x;
    if (t < B_ROWS) out[t] = funkey(g_umax[t]);
}

// ================= host =================
extern "C" void kernel_launch(void* const* d_in, const int* in_sizes, int n_in,
                              void* d_out, int out_size) {
    const float *memx = 0, *value = 0, *W1 = 0, *b1 = 0, *W2 = 0, *b2 = 0,
                *W3 = 0, *b3 = 0, *W4 = 0, *b4 = 0;
    for (int i = 0; i < n_in; i++) {
        const float* p = (const float*)d_in[i];
        switch (in_sizes[i]) {
            case M_ROWS * D_IN: memx = p; break;
            case B_ROWS * D_IN: value = p; break;
            case H1N * D_IN:    W1 = p; break;
            case H1N:           b1 = p; break;
            case H2N * H1N:     W2 = p; break;
            case H2N:           b2 = p; break;
            case H3N * H2N:     W3 = p; break;
            case H3N:           b3 = p; break;
            case D_IN * H3N:    W4 = p; break;
            case D_IN:          b4 = p; break;
            default: break;
        }
    }

    cudaFuncSetAttribute(layer1_kernel, cudaFuncAttributeMaxDynamicSharedMemorySize, L1_SMEM);
    cudaFuncSetAttribute(gemm_kernel<2>, cudaFuncAttributeMaxDynamicSharedMemorySize, GEMM2_SMEM);
    cudaFuncSetAttribute(gemm_kernel<3>, cudaFuncAttributeMaxDynamicSharedMemorySize, G3_SMEM);
    cudaFuncSetAttribute(sim_kernel, cudaFuncAttributeMaxDynamicSharedMemorySize, SIM_SMEM);

    prep_all_kernel<<<148, 256>>>(W2, W3, value);
    layer1_kernel<<<M_ROWS / 128, 256, L1_SMEM>>>(memx, W1, b1);
    gemm_kernel<2><<<dim3(M_ROWS / 128, 5), 256, GEMM2_SMEM>>>(b2, 0, 0);
    gemm_kernel<3><<<dim3(M_ROWS / 128, 1), 256, G3_SMEM>>>(b3, W4, b4);
    sim_kernel<<<M_ROWS / 128, 256, SIM_SMEM>>>();
    finish_kernel<<<B_ROWS / 256, 256>>>((float*)d_out);
}

// round 16
// speedup vs baseline: 1.0864x; 1.0864x over previous
#include <cuda_runtime.h>
#include <cuda_fp16.h>
#include <math.h>
#include <stdint.h>

#define M_ROWS 65536
#define B_ROWS 2048
#define D_IN   13
#define H1N    300
#define H2N    600
#define H3N    100
#define EPS_F  1e-8f
#define SCALE_F 23.0f
#define SLOPE  0.01f

extern __shared__ char dynsmem[];

// ============ scratch (device globals; no allocations) ============
__device__ uint4 g_A2h[65536ULL * 40];   // [65536][320] fp16
__device__ uint4 g_A3h[65536ULL * 80];   // [65536][640] fp16
__device__ uint4 g_W2h[640 * 40];
__device__ uint4 g_W2l[640 * 40];
__device__ uint4 g_W3h[128 * 80];
__device__ uint4 g_W3l[128 * 80];
__device__ uint4 g_vns[B_ROWS * 4];      // [Vh|Vh], 32 fp16/row
__device__ uint4 g_t1s[65536ULL * 4];    // [Th|Tl], 32 fp16/row
__device__ unsigned int g_umax[B_ROWS];

__device__ __forceinline__ unsigned fkey(float f) {
    unsigned b = __float_as_uint(f);
    return (b & 0x80000000u) ? ~b : (b | 0x80000000u);
}
__device__ __forceinline__ float funkey(unsigned u) {
    unsigned b = (u & 0x80000000u) ? (u ^ 0x80000000u) : ~u;
    return __uint_as_float(b);
}
__device__ __forceinline__ uint32_t pk2h(float a, float b) {
    __half2 t = __floats2half2_rn(a, b);
    return *reinterpret_cast<uint32_t*>(&t);
}
__device__ __forceinline__ uint32_t smem_u32(const void* p) {
    uint32_t a;
    asm("{ .reg .u64 t; cvta.to.shared.u64 t, %1; cvt.u32.u64 %0, t; }" : "=r"(a) : "l"(p));
    return a;
}
__device__ __forceinline__ void mma16816(float* d, const uint32_t* a, const uint32_t* b) {
    asm volatile(
        "mma.sync.aligned.m16n8k16.row.col.f32.f16.f16.f32 "
        "{%0,%1,%2,%3}, {%4,%5,%6,%7}, {%8,%9}, {%0,%1,%2,%3};"
        : "+f"(d[0]), "+f"(d[1]), "+f"(d[2]), "+f"(d[3])
        : "r"(a[0]), "r"(a[1]), "r"(a[2]), "r"(a[3]), "r"(b[0]), "r"(b[1]));
}
__device__ __forceinline__ void ldm_x4(uint32_t* r, uint32_t addr) {
    asm volatile("ldmatrix.sync.aligned.m8n8.x4.shared.b16 {%0,%1,%2,%3}, [%4];"
        : "=r"(r[0]), "=r"(r[1]), "=r"(r[2]), "=r"(r[3]) : "r"(addr));
}
__device__ __forceinline__ void ldm_x2(uint32_t* r, uint32_t addr) {
    asm volatile("ldmatrix.sync.aligned.m8n8.x2.shared.b16 {%0,%1}, [%2];"
        : "=r"(r[0]), "=r"(r[1]) : "r"(addr));
}
__device__ __forceinline__ void cpa16(uint32_t dst, const void* src) {
    asm volatile("cp.async.cg.shared.global [%0], [%1], 16;" :: "r"(dst), "l"(src));
}
#define CP_COMMIT() asm volatile("cp.async.commit_group;" ::: "memory")
#define CP_WAIT(n)  asm volatile("cp.async.wait_group %0;" :: "n"(n) : "memory")

// ---------- merged prep: W2 (0-99), W3 (100-139), vn (140-147) ----------
__global__ void __launch_bounds__(256)
prep_all_kernel(const float* __restrict__ W2, const float* __restrict__ W3,
                const float* __restrict__ value) {
    const int blk = blockIdx.x, tid = threadIdx.x;
    if (blk < 100) {
        int e = blk * 256 + tid;                   // [640][40] uint4
        int n = e / 40, c8 = e % 40;
        union { uint4 v; __half b[8]; } hu, lu;
        #pragma unroll
        for (int t = 0; t < 8; t++) {
            int k = c8 * 8 + t;
            float w = (n < H2N && k < H1N) ? W2[n * H1N + k] : 0.f;
            __half h = __float2half_rn(w);
            hu.b[t] = h;
            lu.b[t] = __float2half_rn(w - __half2float(h));
        }
        g_W2h[e] = hu.v;
        g_W2l[e] = lu.v;
    } else if (blk < 140) {
        int e = (blk - 100) * 256 + tid;           // [128][80] uint4
        int n = e / 80, c8 = e % 80;
        union { uint4 v; __half b[8]; } hu, lu;
        #pragma unroll
        for (int t = 0; t < 8; t++) {
            int k = c8 * 8 + t;
            float w = (n < H3N && k < H2N) ? W3[n * H2N + k] : 0.f;
            __half h = __float2half_rn(w);
            hu.b[t] = h;
            lu.b[t] = __float2half_rn(w - __half2float(h));
        }
        g_W3h[e] = hu.v;
        g_W3l[e] = lu.v;
    } else {
        int t = (blk - 140) * 256 + tid;
        if (t < B_ROWS) {
            float v[16], s = 0.f;
            #pragma unroll
            for (int o = 0; o < 16; o++) v[o] = 0.f;
            #pragma unroll
            for (int o = 0; o < D_IN; o++) { v[o] = value[t * D_IN + o]; s += v[o] * v[o]; }
            float inv = 1.f / fmaxf(sqrtf(s), EPS_F);
            union { uint4 q[4]; uint32_t u[16]; } out;
            #pragma unroll
            for (int o = 0; o < 16; o += 2) {
                uint32_t vh = pk2h(v[o] * inv, v[o + 1] * inv);
                out.u[o / 2]     = vh;
                out.u[8 + o / 2] = vh;
            }
            #pragma unroll
            for (int j = 0; j < 4; j++) g_vns[t * 4 + j] = out.q[j];
            g_umax[t] = 0u;
        }
    }
}

// ---------- layer 1: 13 -> 300 relu, fp16 out ----------
#define L1_SW   0
#define L1_SB   20480
#define L1_SX   21760
#define L1_SMEM 32000
__global__ void __launch_bounds__(256)
layer1_kernel(const float* __restrict__ memx, const float* __restrict__ W1,
              const float* __restrict__ b1) {
    float* sW = (float*)(dynsmem + L1_SW);   // [320][16]
    float* sb = (float*)(dynsmem + L1_SB);   // [320]
    float* sx = (float*)(dynsmem + L1_SX);   // [128][20]
    const int tid = threadIdx.x;
    const int m0 = blockIdx.x * 128;
    const int row = tid & 127, half = tid >> 7;

    for (int i = tid; i < 320 * 16; i += 256) sW[i] = 0.f;
    for (int i = tid; i < 320; i += 256) sb[i] = (i < H1N) ? b1[i] : 0.f;
    for (int i = tid; i < 128 * 20; i += 256) sx[i] = 0.f;
    __syncthreads();
    for (int i = tid; i < H1N * D_IN; i += 256) sW[(i / D_IN) * 16 + (i % D_IN)] = W1[i];
    for (int i = tid; i < 128 * D_IN; i += 256) sx[(i / D_IN) * 20 + (i % D_IN)] = memx[(size_t)m0 * D_IN + i];
    __syncthreads();

    float4 xv[4];
    #pragma unroll
    for (int j = 0; j < 4; j++) xv[j] = *(float4*)(&sx[row * 20 + 4 * j]);

    const size_t rbase = (size_t)(m0 + row) * 40 + half * 20;
    #pragma unroll 1
    for (int gg = 0; gg < 10; gg++) {
        uint4 hq[2];
        #pragma unroll
        for (int g2 = 0; g2 < 2; g2++) {
            union { uint4 v; uint32_t u[4]; } hv;
            #pragma unroll
            for (int p = 0; p < 4; p++) {
                float o2[2];
                #pragma unroll
                for (int e = 0; e < 2; e++) {
                    int c = (half * 20 + gg * 2 + g2) * 8 + p * 2 + e;
                    float acc = sb[c];
                    #pragma unroll
                    for (int j = 0; j < 4; j++) {
                        float4 w = *(float4*)(&sW[c * 16 + 4 * j]);
                        acc += xv[j].x * w.x + xv[j].y * w.y + xv[j].z * w.z + xv[j].w * w.w;
                    }
                    o2[e] = fmaxf(acc, 0.f);
                }
                hv.u[p] = pk2h(o2[0], o2[1]);
            }
            hq[g2] = hv.v;
        }
        g_A2h[rbase + gg * 2] = hq[0];
        g_A2h[rbase + gg * 2 + 1] = hq[1];
    }
}

// ---------- gemm2: R13-style split sections, 3-stage cp.async (measured best) ----------
#define SKEW_B 144
#define G2_STAGE (256 * SKEW_B)                       // 36864
#define GEMM2_SMEM (3 * G2_STAGE)                     // 110592
__global__ void __launch_bounds__(256)
gemm2_kernel(const float* __restrict__ bias) {
    constexpr int KPU = 40, SEC = 5, NK = 10;
    constexpr int STAGE = G2_STAGE, BOFF = 128 * SKEW_B;
    char* sm = dynsmem;
    const uint32_t smb = smem_u32(sm);

    const int tid = threadIdx.x;
    const int wid = tid >> 5, lane = tid & 31;
    const int gid = lane >> 2, tig = lane & 3;
    const int wy = wid >> 2, wx = wid & 3;
    const int m0 = blockIdx.x * 128;
    const int n0 = blockIdx.y * 128;

    float acc[4][4][4];
    #pragma unroll
    for (int mi = 0; mi < 4; mi++)
        #pragma unroll
        for (int ni = 0; ni < 4; ni++)
            #pragma unroll
            for (int q = 0; q < 4; q++) acc[mi][ni][q] = 0.f;

    const int lrow = lane & 15, lkh = lane >> 4;
    uint32_t aoff[4], boff[2];
    #pragma unroll
    for (int mi = 0; mi < 4; mi++)
        aoff[mi] = smb + (wy * 64 + mi * 16 + lrow) * SKEW_B + lkh * 16;
    #pragma unroll
    for (int p = 0; p < 2; p++)
        boff[p] = smb + BOFF + (wx * 32 + p * 16 + lrow) * SKEW_B + lkh * 16;

    auto issue_copy = [&](int kc, int st) {
        int sec = kc / SEC, idx = kc % SEC;
        const uint4* Wsrc = sec ? g_W2l : g_W2h;
        int k0u = idx * 8;
        uint32_t sb0 = smb + st * STAGE;
        #pragma unroll
        for (int j = 0; j < 8; j++) {
            int u = tid + j * 256;
            int row = u >> 3, uu = u & 7;
            const uint4* src = (row < 128)
                ? &g_A2h[(size_t)(m0 + row) * KPU + k0u + uu]
                : &Wsrc[(size_t)(n0 + row - 128) * KPU + k0u + uu];
            uint32_t dst = (row < 128)
                ? sb0 + row * SKEW_B + uu * 16
                : sb0 + BOFF + (row - 128) * SKEW_B + uu * 16;
            cpa16(dst, src);
        }
        CP_COMMIT();
    };
    auto compute = [&](int st) {
        const uint32_t sb0 = st * STAGE;
        #pragma unroll
        for (int ks = 0; ks < 4; ks++) {
            const uint32_t ko = sb0 + ks * 32;
            uint32_t af[4][4], bf[4][2];
            #pragma unroll
            for (int p = 0; p < 2; p++) {
                uint32_t r4[4];
                ldm_x4(r4, boff[p] + ko);
                bf[2 * p][0] = r4[0]; bf[2 * p + 1][0] = r4[1];
                bf[2 * p][1] = r4[2]; bf[2 * p + 1][1] = r4[3];
            }
            #pragma unroll
            for (int mi = 0; mi < 4; mi++) ldm_x4(af[mi], aoff[mi] + ko);
            #pragma unroll
            for (int mi = 0; mi < 4; mi++)
                #pragma unroll
                for (int ni = 0; ni < 4; ni++)
                    mma16816(acc[mi][ni], af[mi], bf[ni]);
        }
    };

    issue_copy(0, 0);
    issue_copy(1, 1);
    for (int kc = 0; kc < NK; kc++) {
        if (kc + 1 < NK) { CP_WAIT(1); } else { CP_WAIT(0); }
        __syncthreads();
        if (kc + 2 < NK) issue_copy(kc + 2, (kc + 2) % 3);
        compute(kc % 3);
    }

    #pragma unroll
    for (int mi = 0; mi < 4; mi++) {
        #pragma unroll
        for (int ni = 0; ni < 4; ni++) {
            int r0 = m0 + wy * 64 + mi * 16 + gid;
            int c  = n0 + wx * 32 + ni * 8 + tig * 2;
            if (c < H2N) {
                float bv0 = __ldg(&bias[c]), bv1 = __ldg(&bias[c + 1]);
                #pragma unroll
                for (int h = 0; h < 2; h++) {
                    int r = r0 + h * 8;
                    float v0 = acc[mi][ni][h * 2 + 0] + bv0;
                    float v1 = acc[mi][ni][h * 2 + 1] + bv1;
                    v0 = v0 > 0.f ? v0 : SLOPE * v0;
                    v1 = v1 > 0.f ? v1 : SLOPE * v1;
                    ((uint32_t*)g_A3h)[(size_t)r * 320 + (c >> 1)] = pk2h(v0, v1);
                }
            }
        }
    }
}

// ---------- gemm3: R14-style merged [A|Wh|Wl] 2-stage + fused tail (measured best) ----------
#define G3_STAGE ((128 + 208) * SKEW_B)               // 48384
#define G3_W4   (2 * G3_STAGE)                        // 96768
#define G3_B4   (G3_W4 + 5200)
#define G3_SMEM (G3_B4 + 64)                          // 102032
__global__ void __launch_bounds__(256)
gemm3_kernel(const float* __restrict__ bias,
             const float* __restrict__ W4, const float* __restrict__ b4) {
    constexpr int KPU = 80, NK = 10, NB = 104, NI = 13;
    constexpr int STAGE = G3_STAGE, BOFF = 128 * SKEW_B, WLOFF = NB * SKEW_B;
    char* sm = dynsmem;
    const uint32_t smb = smem_u32(sm);

    const int tid = threadIdx.x;
    const int wid = tid >> 5, lane = tid & 31;
    const int gid = lane >> 2, tig = lane & 3;
    const int wy = wid;
    const int m0 = blockIdx.x * 128;
    const int n0 = 0;

    {
        float* sW4 = (float*)(sm + G3_W4);
        float* sb4 = (float*)(sm + G3_B4);
        for (int i = tid; i < D_IN * H3N; i += 256) sW4[i] = W4[i];
        if (tid < D_IN) sb4[tid] = b4[tid];
    }

    float acc[NI][4];
    #pragma unroll
    for (int ni = 0; ni < NI; ni++)
        #pragma unroll
        for (int q = 0; q < 4; q++) acc[ni][q] = 0.f;

    const int lrow = lane & 15, lkh = lane >> 4;
    uint32_t aoff = smb + (wy * 16 + lrow) * SKEW_B + lkh * 16;
    uint32_t boff[7];
    #pragma unroll
    for (int p = 0; p < 6; p++)
        boff[p] = smb + BOFF + (p * 16 + lrow) * SKEW_B + lkh * 16;
    {
        int l16 = lane & 15;
        boff[6] = smb + BOFF + (96 + (l16 & 7)) * SKEW_B + (l16 >> 3) * 16;
    }

    constexpr int TOT8 = (128 + 2 * NB) * 8;          // 2688
    constexpr int NLD = (TOT8 + 255) / 256;           // 11
    auto issue_copy = [&](int kc, int st) {
        int k0u = kc * 8;
        uint32_t sb0 = smb + st * STAGE;
        #pragma unroll
        for (int j = 0; j < NLD; j++) {
            int u = tid + j * 256;
            if (u < TOT8) {
                int row = u >> 3, uu = u & 7;
                const uint4* src;
                uint32_t dst;
                if (row < 128) {
                    src = &g_A3h[(size_t)(m0 + row) * KPU + k0u + uu];
                    dst = sb0 + row * SKEW_B + uu * 16;
                } else if (row < 128 + NB) {
                    src = &g_W3h[(size_t)(row - 128) * KPU + k0u + uu];
                    dst = sb0 + BOFF + (row - 128) * SKEW_B + uu * 16;
                } else {
                    src = &g_W3l[(size_t)(row - 128 - NB) * KPU + k0u + uu];
                    dst = sb0 + BOFF + WLOFF + (row - 128 - NB) * SKEW_B + uu * 16;
                }
                cpa16(dst, src);
            }
        }
        CP_COMMIT();
    };
    auto load_bf = [&](uint32_t ko, uint32_t (&bf)[NI][2]) {
        #pragma unroll
        for (int p = 0; p < 6; p++) {
            uint32_t r4[4];
            ldm_x4(r4, boff[p] + ko);
            bf[2 * p][0] = r4[0]; bf[2 * p + 1][0] = r4[1];
            bf[2 * p][1] = r4[2]; bf[2 * p + 1][1] = r4[3];
        }
        ldm_x2(bf[12], boff[6] + ko);
    };
    auto compute = [&](int st) {
        const uint32_t sb0 = st * STAGE;
        #pragma unroll
        for (int ks = 0; ks < 4; ks++) {
            const uint32_t ko = sb0 + ks * 32;
            uint32_t af[4];
            ldm_x4(af, aoff + ko);
            uint32_t bf[NI][2];
            load_bf(ko, bf);
            #pragma unroll
            for (int ni = 0; ni < NI; ni++) mma16816(acc[ni], af, bf[ni]);
            load_bf(ko + WLOFF, bf);
            #pragma unroll
            for (int ni = 0; ni < NI; ni++) mma16816(acc[ni], af, bf[ni]);
        }
    };

    issue_copy(0, 0);
    issue_copy(1, 1);
    for (int kc = 0; kc < NK; kc++) {
        if (kc + 1 < NK) { CP_WAIT(1); } else { CP_WAIT(0); }
        __syncthreads();
        compute(kc & 1);
        __syncthreads();
        if (kc + 2 < NK) issue_copy(kc + 2, kc & 1);
    }

    // ---- fused tail: h3 -> smem, layer4 + normalize -> g_t1s split ----
    __syncthreads();
    float* h3s = (float*)sm;             // [128][106]
    #pragma unroll
    for (int ni = 0; ni < NI; ni++) {
        int c = ni * 8 + tig * 2;
        float bv0 = (c < H3N) ? __ldg(&bias[c]) : 0.f;
        float bv1 = (c + 1 < H3N) ? __ldg(&bias[c + 1]) : 0.f;
        #pragma unroll
        for (int h = 0; h < 2; h++) {
            int r = wy * 16 + gid + h * 8;
            float v0 = fmaxf(acc[ni][h * 2 + 0] + bv0, 0.f);
            float v1 = fmaxf(acc[ni][h * 2 + 1] + bv1, 0.f);
            *(float2*)(&h3s[r * 106 + c]) = make_float2(v0, v1);
        }
    }
    __syncthreads();
    if (tid < 128) {
        const float* sW4 = (const float*)(sm + G3_W4);
        const float* sb4 = (const float*)(sm + G3_B4);
        int r = tid;
        float o[D_IN];
        #pragma unroll
        for (int oo = 0; oo < D_IN; oo++) o[oo] = sb4[oo];
        #pragma unroll 4
        for (int k = 0; k < H3N; k++) {
            float hv = h3s[r * 106 + k];
            #pragma unroll
            for (int oo = 0; oo < D_IN; oo++) o[oo] += hv * sW4[oo * H3N + k];
        }
        float s = 0.f;
        #pragma unroll
        for (int oo = 0; oo < D_IN; oo++) {
            o[oo] = o[oo] > 0.f ? o[oo] : SLOPE * o[oo];
            s += o[oo] * o[oo];
        }
        float inv = 1.f / fmaxf(sqrtf(s), EPS_F);
        float t[16];
        #pragma unroll
        for (int oo = 0; oo < 16; oo++) t[oo] = (oo < D_IN) ? o[oo] * inv : 0.f;
        union { uint4 q[4]; uint32_t u[16]; } out;
        #pragma unroll
        for (int oo = 0; oo < 16; oo += 2) {
            float ah = __half2float(__float2half_rn(t[oo]));
            float bh = __half2float(__float2half_rn(t[oo + 1]));
            out.u[oo / 2]     = pk2h(t[oo], t[oo + 1]);               // Th
            out.u[8 + oo / 2] = pk2h(t[oo] - ah, t[oo + 1] - bh);     // Tl
        }
        #pragma unroll
        for (int j = 0; j < 4; j++) g_t1s[(size_t)(m0 + r) * 4 + j] = out.q[j];
    }
}

// ---------- similarity via fp16 mma: Vh * (Th + Tl) ----------
#define SIM_SV  0
#define SIM_ST  (2048 * 80)
#define SIM_SMEM (SIM_ST + 128 * 80)       // 174080
__global__ void __launch_bounds__(256, 1)
sim_kernel() {
    char* sm = dynsmem;
    char* sv  = sm + SIM_SV;    // [2048][80B]
    char* st1 = sm + SIM_ST;    // [128][80B]
    const int tid = threadIdx.x;
    const int wid = tid >> 5, lane = tid & 31;
    const int gid = lane >> 2, tig = lane & 3;
    const int wy = wid >> 2, wx = wid & 3;
    const int n0 = blockIdx.x * 128;

    for (int i = tid; i < B_ROWS * 4; i += 256) {
        int r = i >> 2, q = i & 3;
        *(uint4*)(sv + r * 80 + q * 16) = g_vns[i];
    }
    for (int i = tid; i < 128 * 4; i += 256) {
        int r = i >> 2, q = i & 3;
        *(uint4*)(st1 + r * 80 + q * 16) = g_t1s[(size_t)n0 * 4 + i];
    }
    __syncthreads();

    uint32_t sbf[2][4][2];
    #pragma unroll
    for (int s = 0; s < 2; s++)
        #pragma unroll
        for (int ni = 0; ni < 4; ni++) {
            int n = wx * 32 + ni * 8 + gid;
            sbf[s][ni][0] = *(const uint32_t*)(st1 + n * 80 + s * 32 + tig * 4);
            sbf[s][ni][1] = *(const uint32_t*)(st1 + n * 80 + s * 32 + 16 + tig * 4);
        }

    for (int c = 0; c < 8; c++) {
        float acc[8][4][4];
        #pragma unroll
        for (int mi = 0; mi < 8; mi++)
            #pragma unroll
            for (int ni = 0; ni < 4; ni++)
                #pragma unroll
                for (int q = 0; q < 4; q++) acc[mi][ni][q] = 0.f;

        const char* va = sv + (c * 256 + wy * 128) * 80;
        #pragma unroll
        for (int s = 0; s < 2; s++) {
            #pragma unroll
            for (int mi = 0; mi < 8; mi++) {
                int r = mi * 16 + gid;
                uint32_t af[4];
                af[0] = *(const uint32_t*)(va + r * 80 + s * 32 + tig * 4);
                af[1] = *(const uint32_t*)(va + (r + 8) * 80 + s * 32 + tig * 4);
                af[2] = *(const uint32_t*)(va + r * 80 + s * 32 + 16 + tig * 4);
                af[3] = *(const uint32_t*)(va + (r + 8) * 80 + s * 32 + 16 + tig * 4);
                #pragma unroll
                for (int ni = 0; ni < 4; ni++)
                    mma16816(acc[mi][ni], af, sbf[s][ni]);
            }
        }
        #pragma unroll
        for (int mi = 0; mi < 8; mi++) {
            #pragma unroll
            for (int h = 0; h < 2; h++) {
                float mx = -3.4e38f;
                #pragma unroll
                for (int ni = 0; ni < 4; ni++)
                    mx = fmaxf(mx, fmaxf(acc[mi][ni][h * 2], acc[mi][ni][h * 2 + 1]));
                mx = fmaxf(mx, __shfl_xor_sync(0xFFFFFFFF, mx, 1));
                mx = fmaxf(mx, __shfl_xor_sync(0xFFFFFFFF, mx, 2));
                if (tig == 0) {
                    int row = c * 256 + wy * 128 + mi * 16 + gid + 8 * h;
                    atomicMax(&g_umax[row], fkey(SCALE_F * mx));
                }
            }
        }
    }
}

__global__ void finish_kernel(float* __restrict__ out) {
    int t = blockIdx.x * blockDim.x + threadIdx.x;
    if (t < B_ROWS) out[t] = funkey(g_umax[t]);
}

// ================= host =================
extern "C" void kernel_launch(void* const* d_in, const int* in_sizes, int n_in,
                              void* d_out, int out_size) {
    const float *memx = 0, *value = 0, *W1 = 0, *b1 = 0, *W2 = 0, *b2 = 0,
                *W3 = 0, *b3 = 0, *W4 = 0, *b4 = 0;
    for (int i = 0; i < n_in; i++) {
        const float* p = (const float*)d_in[i];
        switch (in_sizes[i]) {
            case M_ROWS * D_IN: memx = p; break;
            case B_ROWS * D_IN: value = p; break;
            case H1N * D_IN:    W1 = p; break;
            case H1N:           b1 = p; break;
            case H2N * H1N:     W2 = p; break;
            case H2N:           b2 = p; break;
            case H3N * H2N:     W3 = p; break;
            case H3N:           b3 = p; break;
            case D_IN * H3N:    W4 = p; break;
            case D_IN:          b4 = p; break;
            default: break;
        }
    }

    cudaFuncSetAttribute(layer1_kernel, cudaFuncAttributeMaxDynamicSharedMemorySize, L1_SMEM);
    cudaFuncSetAttribute(gemm2_kernel, cudaFuncAttributeMaxDynamicSharedMemorySize, GEMM2_SMEM);
    cudaFuncSetAttribute(gemm3_kernel, cudaFuncAttributeMaxDynamicSharedMemorySize, G3_SMEM);
    cudaFuncSetAttribute(sim_kernel, cudaFuncAttributeMaxDynamicSharedMemorySize, SIM_SMEM);

    prep_all_kernel<<<148, 256>>>(W2, W3, value);
    layer1_kernel<<<M_ROWS / 128, 256, L1_SMEM>>>(memx, W1, b1);
    gemm2_kernel<<<dim3(M_ROWS / 128, 5), 256, GEMM2_SMEM>>>(b2);
    gemm3_kernel<<<M_ROWS / 128, 256, G3_SMEM>>>(b3, W4, b4);
    sim_kernel<<<M_ROWS / 128, 256, SIM_SMEM>>>();
    finish_kernel<<<B_ROWS / 256, 256>>>((float*)d_out);
}